// round 4
// baseline (speedup 1.0000x reference)
#include <cuda_runtime.h>
#include <cuda_bf16.h>

// IoU kernel: elementwise over N boxes, A=5 anchors.
// Inputs (metadata order):
//   d_in[0]: cell_nos  int32  [N,2]
//   d_in[1]: output    float  [N,5,5]
//   d_in[2]: target    float  [N,5]
// Output: float [N,5]
//
// HBM-streaming problem (~592MB total traffic). Strategy: stage per-block
// chunks into shared memory with coalesced float4 loads, compute from smem
// (conflict-free: strides 25 and 5 are coprime with 32), write contiguous
// 5-float runs per thread (warp covers contiguous 640B -> full sectors).

#define YI 20.0f
#define BPB 256           // boxes per block == threads per block
#define A 5               // anchors

__global__ __launch_bounds__(BPB) void iou_kernel(
    const int* __restrict__ cell_nos,
    const float* __restrict__ output,
    const float* __restrict__ target,
    float* __restrict__ res,
    int n)
{
    __shared__ float s_out[BPB * 25];   // 25600 B
    __shared__ float s_tgt[BPB * 5];    //  5120 B
    __shared__ int   s_cell[BPB * 2];   //  2048 B

    const int tid  = threadIdx.x;
    const int base = blockIdx.x * BPB;

    if (base + BPB <= n) {
        // Full block: vectorized staging. All global offsets are 16B-aligned:
        // base*25*4B, base*5*4B, base*2*4B are multiples of 16 for base%4==0.
        const float4* g_out = reinterpret_cast<const float4*>(output + (size_t)base * 25);
        const float4* g_tgt = reinterpret_cast<const float4*>(target + (size_t)base * 5);
        const int4*   g_cel = reinterpret_cast<const int4*>(cell_nos + (size_t)base * 2);
        float4* so = reinterpret_cast<float4*>(s_out);
        float4* st = reinterpret_cast<float4*>(s_tgt);
        int4*   sc = reinterpret_cast<int4*>(s_cell);

        #pragma unroll
        for (int i = 0; i < (BPB * 25 / 4 + BPB - 1) / BPB; i++) {
            int idx = tid + i * BPB;
            if (idx < BPB * 25 / 4) so[idx] = g_out[idx];
        }
        #pragma unroll
        for (int i = 0; i < (BPB * 5 / 4 + BPB - 1) / BPB; i++) {
            int idx = tid + i * BPB;
            if (idx < BPB * 5 / 4) st[idx] = g_tgt[idx];
        }
        if (tid < BPB * 2 / 4) sc[tid] = g_cel[tid];
    } else {
        // Tail block: scalar guarded staging.
        int nb = n - base;
        if (nb < 0) nb = 0;
        for (int idx = tid; idx < nb * 25; idx += BPB)
            s_out[idx] = output[(size_t)base * 25 + idx];
        for (int idx = tid; idx < nb * 5; idx += BPB)
            s_tgt[idx] = target[(size_t)base * 5 + idx];
        for (int idx = tid; idx < nb * 2; idx += BPB)
            s_cell[idx] = cell_nos[(size_t)base * 2 + idx];
    }
    __syncthreads();

    const int box = base + tid;
    if (box >= n) return;

    // Cell centers
    const float ci = (float)s_cell[2 * tid]     * YI + YI * 0.5f;
    const float cj = (float)s_cell[2 * tid + 1] * YI + YI * 0.5f;

    // Ground-truth box corners
    const float* t = &s_tgt[5 * tid];
    {
        // fallthrough to locals below
    }
    const float g_dx = t[1], g_dy = t[2], g_h = t[3] * YI, g_w = t[4] * YI;
    const float gxc = ci + g_dx * YI;   // "x_center"
    const float gyc = cj + g_dy * YI;   // "y_center"
    const float gx1 = gyc - g_w * 0.5f;
    const float gy1 = gxc - g_h * 0.5f;
    const float gx2 = gyc + g_w * 0.5f;
    const float gy2 = gxc + g_h * 0.5f;
    const float area_g = (gx2 - gx1) * (gy2 - gy1);

    float r[A];
    #pragma unroll
    for (int a = 0; a < A; a++) {
        const float* o = &s_out[25 * tid + 5 * a];
        const float p_h = o[3] * YI, p_w = o[4] * YI;
        const float pxc = ci + o[1] * YI;
        const float pyc = cj + o[2] * YI;
        const float px1 = pyc - p_w * 0.5f;
        const float py1 = pxc - p_h * 0.5f;
        const float px2 = pyc + p_w * 0.5f;
        const float py2 = pxc + p_h * 0.5f;
        const float area_p = (px2 - px1) * (py2 - py1);

        const float lx = fmaxf(px1, gx1);
        const float ly = fmaxf(py1, gy1);
        const float rx = fminf(px2, gx2);
        const float ry = fminf(py2, gy2);
        const float iw = fmaxf(rx - lx, 0.0f);
        const float ih = fmaxf(ry - ly, 0.0f);
        const float inter = iw * ih;
        const float uni = area_p + area_g - inter;
        r[a] = __fdividef(inter, uni);
    }

    float* dst = res + (size_t)box * A;
    #pragma unroll
    for (int a = 0; a < A; a++) dst[a] = r[a];
}

extern "C" void kernel_launch(void* const* d_in, const int* in_sizes, int n_in,
                              void* d_out, int out_size) {
    const int*   cell_nos = (const int*)d_in[0];
    const float* output   = (const float*)d_in[1];
    const float* target   = (const float*)d_in[2];
    float*       res      = (float*)d_out;

    const int n = in_sizes[0] / 2;  // cell_nos is [N,2]
    const int grid = (n + BPB - 1) / BPB;
    iou_kernel<<<grid, BPB>>>(cell_nos, output, target, res, n);
}

// round 5
// speedup vs baseline: 1.0525x; 1.0525x over previous
#include <cuda_runtime.h>
#include <cuda_bf16.h>

// IoU kernel: elementwise over N boxes, A=5 anchors.
// Inputs (metadata order):
//   d_in[0]: cell_nos  int32  [N,2]
//   d_in[1]: output    float  [N,5,5]
//   d_in[2]: target    float  [N,5]
// Output: float [N,5]
//
// HBM-streaming problem (~592MB total traffic). Strategy:
//  - stage per-block chunks into shared memory with coalesced float4 __ldcs loads
//  - compute from smem (strides 25 and 5 coprime with 32 -> conflict-free)
//  - stage results back into smem (reusing s_tgt: same footprint, no hazard)
//  - drain with coalesced float4 __stcs stores (evict-first: zero reuse stream)

#define YI 20.0f
#define BPB 256           // boxes per block == threads per block
#define A 5               // anchors

__global__ __launch_bounds__(BPB) void iou_kernel(
    const int* __restrict__ cell_nos,
    const float* __restrict__ output,
    const float* __restrict__ target,
    float* __restrict__ res,
    int n)
{
    __shared__ float s_out[BPB * 25];   // 25600 B
    __shared__ float s_tgt[BPB * 5];    //  5120 B (reused as result buffer)
    __shared__ int   s_cell[BPB * 2];   //  2048 B

    const int tid  = threadIdx.x;
    const int base = blockIdx.x * BPB;
    const bool full = (base + BPB <= n);

    if (full) {
        // Full block: vectorized streaming staging. All global base offsets are
        // 16B-aligned (base*25*4, base*5*4, base*2*4 are multiples of 16).
        const float4* g_out = reinterpret_cast<const float4*>(output + (size_t)base * 25);
        const float4* g_tgt = reinterpret_cast<const float4*>(target + (size_t)base * 5);
        const int4*   g_cel = reinterpret_cast<const int4*>(cell_nos + (size_t)base * 2);
        float4* so = reinterpret_cast<float4*>(s_out);
        float4* st = reinterpret_cast<float4*>(s_tgt);
        int4*   sc = reinterpret_cast<int4*>(s_cell);

        #pragma unroll
        for (int i = 0; i < (BPB * 25 / 4 + BPB - 1) / BPB; i++) {
            int idx = tid + i * BPB;
            if (idx < BPB * 25 / 4) so[idx] = __ldcs(&g_out[idx]);
        }
        #pragma unroll
        for (int i = 0; i < (BPB * 5 / 4 + BPB - 1) / BPB; i++) {
            int idx = tid + i * BPB;
            if (idx < BPB * 5 / 4) st[idx] = __ldcs(&g_tgt[idx]);
        }
        if (tid < BPB * 2 / 4) sc[tid] = __ldcs(&g_cel[tid]);
    } else {
        // Tail block: scalar guarded staging.
        int nb = n - base;
        if (nb < 0) nb = 0;
        for (int idx = tid; idx < nb * 25; idx += BPB)
            s_out[idx] = output[(size_t)base * 25 + idx];
        for (int idx = tid; idx < nb * 5; idx += BPB)
            s_tgt[idx] = target[(size_t)base * 5 + idx];
        for (int idx = tid; idx < nb * 2; idx += BPB)
            s_cell[idx] = cell_nos[(size_t)base * 2 + idx];
    }
    __syncthreads();

    const int box = base + tid;
    float r[A];

    if (box < n) {
        // Cell centers
        const float ci = (float)s_cell[2 * tid]     * YI + YI * 0.5f;
        const float cj = (float)s_cell[2 * tid + 1] * YI + YI * 0.5f;

        // Ground-truth box corners
        const float* t = &s_tgt[5 * tid];
        const float g_h = t[3] * YI, g_w = t[4] * YI;
        const float gxc = ci + t[1] * YI;   // "x_center"
        const float gyc = cj + t[2] * YI;   // "y_center"
        const float gx1 = gyc - g_w * 0.5f;
        const float gy1 = gxc - g_h * 0.5f;
        const float gx2 = gyc + g_w * 0.5f;
        const float gy2 = gxc + g_h * 0.5f;
        const float area_g = (gx2 - gx1) * (gy2 - gy1);

        #pragma unroll
        for (int a = 0; a < A; a++) {
            const float* o = &s_out[25 * tid + 5 * a];
            const float p_h = o[3] * YI, p_w = o[4] * YI;
            const float pxc = ci + o[1] * YI;
            const float pyc = cj + o[2] * YI;
            const float px1 = pyc - p_w * 0.5f;
            const float py1 = pxc - p_h * 0.5f;
            const float px2 = pyc + p_w * 0.5f;
            const float py2 = pxc + p_h * 0.5f;
            const float area_p = (px2 - px1) * (py2 - py1);

            const float lx = fmaxf(px1, gx1);
            const float ly = fmaxf(py1, gy1);
            const float rx = fminf(px2, gx2);
            const float ry = fminf(py2, gy2);
            const float iw = fmaxf(rx - lx, 0.0f);
            const float ih = fmaxf(ry - ly, 0.0f);
            const float inter = iw * ih;
            const float uni = area_p + area_g - inter;
            r[a] = __fdividef(inter, uni);
        }

        // Stage results into s_tgt. Thread tid overwrites exactly the region
        // [5*tid, 5*tid+5) that only it read above -> no cross-thread hazard.
        #pragma unroll
        for (int a = 0; a < A; a++) s_tgt[5 * tid + a] = r[a];
    }
    __syncthreads();

    if (full) {
        // Coalesced vectorized streaming store: BPB*5/4 = 320 float4.
        float4* g_res = reinterpret_cast<float4*>(res + (size_t)base * 5);
        const float4* sr = reinterpret_cast<const float4*>(s_tgt);
        #pragma unroll
        for (int i = 0; i < (BPB * 5 / 4 + BPB - 1) / BPB; i++) {
            int idx = tid + i * BPB;
            if (idx < BPB * 5 / 4) __stcs(&g_res[idx], sr[idx]);
        }
    } else if (box < n) {
        float* dst = res + (size_t)box * A;
        #pragma unroll
        for (int a = 0; a < A; a++) dst[a] = r[a];
    }
}

extern "C" void kernel_launch(void* const* d_in, const int* in_sizes, int n_in,
                              void* d_out, int out_size) {
    const int*   cell_nos = (const int*)d_in[0];
    const float* output   = (const float*)d_in[1];
    const float* target   = (const float*)d_in[2];
    float*       res      = (float*)d_out;

    const int n = in_sizes[0] / 2;  // cell_nos is [N,2]
    const int grid = (n + BPB - 1) / BPB;
    iou_kernel<<<grid, BPB>>>(cell_nos, output, target, res, n);
}

// round 8
// speedup vs baseline: 1.3262x; 1.2600x over previous
#include <cuda_runtime.h>
#include <cuda_bf16.h>
#include <cstdint>

// IoU kernel: elementwise over N boxes, A=5 anchors.
// Inputs (metadata order):
//   d_in[0]: cell_nos  int32  [N,2]
//   d_in[1]: output    float  [N,5,5]
//   d_in[2]: target    float  [N,5]
// Output: float [N,5]
//
// HBM-streaming problem (~592MB). This round: stage chunks via cp.async.bulk
// (TMA path, bypasses LSU/L1tex wavefront queue + register round-trip),
// compute from smem (strides 25/5 coprime with 32 -> conflict-free),
// drain results with one bulk smem->gmem store per block.

#define YI 20.0f
#define BPB 256           // boxes per block == threads per block
#define A 5               // anchors

#define OUT_BYTES (BPB * 25 * 4)   // 25600
#define TGT_BYTES (BPB * 5 * 4)    //  5120
#define CEL_BYTES (BPB * 2 * 4)    //  2048
#define TX_TOTAL  (OUT_BYTES + TGT_BYTES + CEL_BYTES)  // 32768

__global__ __launch_bounds__(BPB) void iou_kernel(
    const int* __restrict__ cell_nos,
    const float* __restrict__ output,
    const float* __restrict__ target,
    float* __restrict__ res,
    int n)
{
    __shared__ alignas(16) float s_out[BPB * 25];   // 25600 B
    __shared__ alignas(16) float s_tgt[BPB * 5];    //  5120 B (reused as result buffer)
    __shared__ alignas(16) int   s_cell[BPB * 2];   //  2048 B
    __shared__ alignas(8)  unsigned long long mbar;

    const int tid  = threadIdx.x;
    const int base = blockIdx.x * BPB;
    const bool full = (base + BPB <= n);

    if (full) {
        const uint32_t mbar_a = (uint32_t)__cvta_generic_to_shared(&mbar);
        if (tid == 0) {
            asm volatile("mbarrier.init.shared::cta.b64 [%0], %1;"
                         :: "r"(mbar_a), "r"(1) : "memory");
        }
        __syncthreads();
        if (tid == 0) {
            asm volatile("mbarrier.arrive.expect_tx.shared::cta.b64 _, [%0], %1;"
                         :: "r"(mbar_a), "r"((uint32_t)TX_TOTAL) : "memory");
            const uint32_t so_a = (uint32_t)__cvta_generic_to_shared(s_out);
            const uint32_t st_a = (uint32_t)__cvta_generic_to_shared(s_tgt);
            const uint32_t sc_a = (uint32_t)__cvta_generic_to_shared(s_cell);
            asm volatile("cp.async.bulk.shared::cta.global.mbarrier::complete_tx::bytes "
                         "[%0], [%1], %2, [%3];"
                         :: "r"(so_a), "l"(output + (size_t)base * 25),
                            "r"((uint32_t)OUT_BYTES), "r"(mbar_a) : "memory");
            asm volatile("cp.async.bulk.shared::cta.global.mbarrier::complete_tx::bytes "
                         "[%0], [%1], %2, [%3];"
                         :: "r"(st_a), "l"(target + (size_t)base * 5),
                            "r"((uint32_t)TGT_BYTES), "r"(mbar_a) : "memory");
            asm volatile("cp.async.bulk.shared::cta.global.mbarrier::complete_tx::bytes "
                         "[%0], [%1], %2, [%3];"
                         :: "r"(sc_a), "l"(cell_nos + (size_t)base * 2),
                            "r"((uint32_t)CEL_BYTES), "r"(mbar_a) : "memory");
        }
        // All threads wait on the mbarrier (phase 0), acquire semantics so the
        // subsequent ld.shared are ordered after TMA delivery.
        {
            uint32_t done;
            asm volatile(
                "{\n\t"
                ".reg .pred p;\n\t"
                "mbarrier.try_wait.parity.acquire.cta.shared::cta.b64 p, [%1], %2;\n\t"
                "selp.b32 %0, 1, 0, p;\n\t"
                "}"
                : "=r"(done) : "r"(mbar_a), "r"(0) : "memory");
            if (!done) {
                asm volatile(
                    "{\n\t"
                    ".reg .pred P1;\n\t"
                    "WAIT_LOOP_%=:\n\t"
                    "mbarrier.try_wait.parity.acquire.cta.shared::cta.b64 P1, [%0], %1, 0x989680;\n\t"
                    "@P1 bra.uni WAIT_DONE_%=;\n\t"
                    "bra.uni WAIT_LOOP_%=;\n\t"
                    "WAIT_DONE_%=:\n\t"
                    "}"
                    :: "r"(mbar_a), "r"(0) : "memory");
            }
        }
    } else {
        // Tail block: scalar guarded staging (n == 4,000,000 = 15625*256, so
        // this path never executes at the bench shape; kept for generality).
        int nb = n - base;
        if (nb < 0) nb = 0;
        for (int idx = tid; idx < nb * 25; idx += BPB)
            s_out[idx] = output[(size_t)base * 25 + idx];
        for (int idx = tid; idx < nb * 5; idx += BPB)
            s_tgt[idx] = target[(size_t)base * 5 + idx];
        for (int idx = tid; idx < nb * 2; idx += BPB)
            s_cell[idx] = cell_nos[(size_t)base * 2 + idx];
        __syncthreads();
    }

    const int box = base + tid;
    float r[A];

    if (box < n) {
        // Cell centers
        const float ci = (float)s_cell[2 * tid]     * YI + YI * 0.5f;
        const float cj = (float)s_cell[2 * tid + 1] * YI + YI * 0.5f;

        // Ground-truth box corners
        const float* t = &s_tgt[5 * tid];
        const float g_h = t[3] * YI, g_w = t[4] * YI;
        const float gxc = ci + t[1] * YI;   // "x_center"
        const float gyc = cj + t[2] * YI;   // "y_center"
        const float gx1 = gyc - g_w * 0.5f;
        const float gy1 = gxc - g_h * 0.5f;
        const float gx2 = gyc + g_w * 0.5f;
        const float gy2 = gxc + g_h * 0.5f;
        const float area_g = (gx2 - gx1) * (gy2 - gy1);

        #pragma unroll
        for (int a = 0; a < A; a++) {
            const float* o = &s_out[25 * tid + 5 * a];
            const float p_h = o[3] * YI, p_w = o[4] * YI;
            const float pxc = ci + o[1] * YI;
            const float pyc = cj + o[2] * YI;
            const float px1 = pyc - p_w * 0.5f;
            const float py1 = pxc - p_h * 0.5f;
            const float px2 = pyc + p_w * 0.5f;
            const float py2 = pxc + p_h * 0.5f;
            const float area_p = (px2 - px1) * (py2 - py1);

            const float lx = fmaxf(px1, gx1);
            const float ly = fmaxf(py1, gy1);
            const float rx = fminf(px2, gx2);
            const float ry = fminf(py2, gy2);
            const float iw = fmaxf(rx - lx, 0.0f);
            const float ih = fmaxf(ry - ly, 0.0f);
            const float inter = iw * ih;
            const float uni = area_p + area_g - inter;
            r[a] = __fdividef(inter, uni);
        }

        // Stage results into s_tgt. Thread tid overwrites exactly the region
        // [5*tid, 5*tid+5) that only it read above -> no cross-thread hazard.
        #pragma unroll
        for (int a = 0; a < A; a++) s_tgt[5 * tid + a] = r[a];
    }
    __syncthreads();

    if (full) {
        // One bulk smem->gmem store for the whole block's 5120B of results.
        if (tid == 0) {
            const uint32_t st_a = (uint32_t)__cvta_generic_to_shared(s_tgt);
            asm volatile("fence.proxy.async.shared::cta;" ::: "memory");
            asm volatile("cp.async.bulk.global.shared::cta.bulk_group [%0], [%1], %2;"
                         :: "l"(res + (size_t)base * 5), "r"(st_a),
                            "r"((uint32_t)TGT_BYTES) : "memory");
            asm volatile("cp.async.bulk.commit_group;" ::: "memory");
            asm volatile("cp.async.bulk.wait_group 0;" ::: "memory");
        }
    } else if (box < n) {
        float* dst = res + (size_t)box * A;
        #pragma unroll
        for (int a = 0; a < A; a++) dst[a] = r[a];
    }
}

extern "C" void kernel_launch(void* const* d_in, const int* in_sizes, int n_in,
                              void* d_out, int out_size) {
    const int*   cell_nos = (const int*)d_in[0];
    const float* output   = (const float*)d_in[1];
    const float* target   = (const float*)d_in[2];
    float*       res      = (float*)d_out;

    const int n = in_sizes[0] / 2;  // cell_nos is [N,2]
    const int grid = (n + BPB - 1) / BPB;
    iou_kernel<<<grid, BPB>>>(cell_nos, output, target, res, n);
}